// round 3
// baseline (speedup 1.0000x reference)
#include <cuda_runtime.h>
#include <math.h>

#define BATCH 2048
#define NC    9605
#define NL    8
#define MAXWL 512
#define NTHR  256

__device__ int           g_wl_count;
__device__ int           g_wl_idx[MAXWL];
__device__ unsigned char g_wl_mask[MAXWL];
__device__ float         g_row_val[BATCH];

__device__ __forceinline__ float sigmoidf_(float v) {
    // v = -1e30 -> expf(1e30) = inf -> result 0 (correct)
    return 1.0f / (1.0f + expf(-v));
}

// ---------------------------------------------------------------------------
// Kernel 1: sniff wl_masks dtype (bool arrays are converted by the harness to
// int32 or float32; uint8 also handled), then compact to (col, 8-bit labelmask).
// Detection reads only the first NL*NC BYTES, which is in-bounds under every
// dtype hypothesis. Fully deterministic.
// ---------------------------------------------------------------------------
__global__ void build_wl_kernel(const void* __restrict__ wlraw) {
    const int tid = threadIdx.x;
    __shared__ int s_bad_int, s_any_int1, s_bad_f, s_any_f1;
    if (tid == 0) { g_wl_count = 0; s_bad_int = 0; s_any_int1 = 0; s_bad_f = 0; s_any_f1 = 0; }
    __syncthreads();

    const int NQ = (NL * NC) / 4;  // 4-byte slots safely readable under any dtype
    const int*   ip = (const int*)wlraw;
    const float* fp = (const float*)wlraw;
    for (int i = tid; i < NQ; i += blockDim.x) {
        int v = ip[i];
        if (v != 0 && v != 1) s_bad_int = 1;
        if (v == 1)           s_any_int1 = 1;
        float f = fp[i];
        if (!(f == 0.0f || f == 1.0f)) s_bad_f = 1;
        if (f == 1.0f)                 s_any_f1 = 1;
    }
    __syncthreads();
    // mode: 2 = float32, 1 = int32, 0 = uint8/bool
    const int mode = (!s_bad_f && s_any_f1) ? 2 : (!s_bad_int ? 1 : 0);
    const unsigned char* up = (const unsigned char*)wlraw;

    for (int c = tid; c < NC; c += blockDim.x) {
        unsigned m = 0;
#pragma unroll
        for (int l = 0; l < NL; ++l) {
            bool on;
            if      (mode == 2) on = (fp[l * NC + c] != 0.0f);
            else if (mode == 1) on = (ip[l * NC + c] != 0);
            else                on = (up[l * NC + c] != 0);
            if (on) m |= (1u << l);
        }
        if (m) {
            int p = atomicAdd(&g_wl_count, 1);
            g_wl_idx[p]  = c;
            g_wl_mask[p] = (unsigned char)m;
        }
    }
}

// ---------------------------------------------------------------------------
// Kernel 2: one block per row. Exact 11th-largest of x (sigmoid is monotone),
// whitelist label maxes, has-positive bits, union max, epilogue.
// ---------------------------------------------------------------------------
__global__ void __launch_bounds__(NTHR)
row_kernel(const float* __restrict__ x, const float* __restrict__ y) {
    const int b   = blockIdx.x;
    const int tid = threadIdx.x;
    const float* xr = x + (size_t)b * NC;
    const float* yr = y + (size_t)b * NC;

    // ---- per-thread top-11 (sorted descending) over strided columns ----
    float t[11];
#pragma unroll
    for (int i = 0; i < 11; ++i) t[i] = -INFINITY;

#pragma unroll 4
    for (int c = tid; c < NC; c += NTHR) {
        float v = __ldg(xr + c);
        if (v > t[10]) {
            int j = 10;
            while (j > 0 && v > t[j - 1]) { t[j] = t[j - 1]; --j; }
            t[j] = v;
        }
    }

    // ---- block merge of sorted 11-lists (tree, exact) ----
    __shared__ float s_top[NTHR * 11];
#pragma unroll
    for (int i = 0; i < 11; ++i) s_top[tid * 11 + i] = t[i];
    __syncthreads();

    for (int off = NTHR / 2; off >= 1; off >>= 1) {
        if (tid < off) {
            const float* bp = &s_top[(tid + off) * 11];
            float o[11];
            int i = 0, j = 0;
#pragma unroll
            for (int k = 0; k < 11; ++k) {
                float av = t[i], bv = bp[j];
                if (av >= bv) { o[k] = av; ++i; } else { o[k] = bv; ++j; }
            }
#pragma unroll
            for (int k = 0; k < 11; ++k) t[k] = o[k];
        }
        __syncthreads();
        if (off > 1 && tid < off) {
#pragma unroll
            for (int k = 0; k < 11; ++k) s_top[tid * 11 + k] = t[k];
        }
        __syncthreads();
    }
    // thread 0 now holds the row's true top-11 in t[]; x11 = t[10]

    // ---- whitelist gather: label maxes, positive bits, union max ----
    const int nwl = g_wl_count;
    float lmax[NL];
#pragma unroll
    for (int l = 0; l < NL; ++l) lmax[l] = -1e30f;
    float    union_x  = -1e30f;
    unsigned pos_bits = 0;

    for (int e = tid; e < nwl; e += NTHR) {
        int      c  = g_wl_idx[e];
        unsigned m  = g_wl_mask[e];
        float    xv = __ldg(xr + c);
        float    yv = __ldg(yr + c);
        union_x = fmaxf(union_x, xv);
        if (yv > 0.0f) pos_bits |= m;
#pragma unroll
        for (int l = 0; l < NL; ++l)
            if (m & (1u << l)) lmax[l] = fmaxf(lmax[l], xv);
    }

    // warp reduction
#pragma unroll
    for (int s = 16; s > 0; s >>= 1) {
#pragma unroll
        for (int l = 0; l < NL; ++l)
            lmax[l] = fmaxf(lmax[l], __shfl_xor_sync(0xffffffffu, lmax[l], s));
        union_x  = fmaxf(union_x, __shfl_xor_sync(0xffffffffu, union_x, s));
        pos_bits |= __shfl_xor_sync(0xffffffffu, pos_bits, s);
    }

    __shared__ float    s_lmax[NTHR / 32][NL];
    __shared__ float    s_un[NTHR / 32];
    __shared__ unsigned s_pb[NTHR / 32];
    const int warp = tid >> 5, lane = tid & 31;
    if (lane == 0) {
#pragma unroll
        for (int l = 0; l < NL; ++l) s_lmax[warp][l] = lmax[l];
        s_un[warp] = union_x;
        s_pb[warp] = pos_bits;
    }
    __syncthreads();

    if (tid == 0) {
#pragma unroll
        for (int w = 1; w < NTHR / 32; ++w) {
#pragma unroll
            for (int l = 0; l < NL; ++l) lmax[l] = fmaxf(lmax[l], s_lmax[w][l]);
            union_x  = fmaxf(union_x, s_un[w]);
            pos_bits |= s_pb[w];
        }

        const float x11   = t[10];
        const float thres = fmaxf(sigmoidf_(x11), 0.5f);   // ALPHA_OTHER

        float correct_x = -1e30f, incorrect_x = -1e30f;
#pragma unroll
        for (int l = 0; l < NL; ++l) {
            if (pos_bits & (1u << l)) correct_x   = fmaxf(correct_x,   lmax[l]);
            else                      incorrect_x = fmaxf(incorrect_x, lmax[l]);
        }

        float x1, x2, coef;
        if (pos_bits) {                         // any_correct
            x1   = sigmoidf_(correct_x);
            // where(any_incorrect, max(sig(inc), thres), thres) == max(sig(inc_or_-1e30), thres)
            x2   = fmaxf(sigmoidf_(incorrect_x), thres);
            coef = 1.0f;
        } else {
            x1   = thres;
            x2   = sigmoidf_(union_x);
            coef = 0.5f;                        // 1 - ALPHA
        }

        const float d    = x2 - x1 + 0.1f;      // ALPHA1
        const float rank = (d > 0.0f ? 2.0f : 1.0f) * sigmoidf_(10.0f * d); // ALPHA2/ALPHA3
        g_row_val[b] = coef * rank;
    }
}

// ---------------------------------------------------------------------------
// Kernel 3: deterministic tree sum -> mean
// ---------------------------------------------------------------------------
__global__ void __launch_bounds__(NTHR)
sum_kernel(float* __restrict__ out) {
    __shared__ float s[NTHR];
    float acc = 0.0f;
    for (int i = threadIdx.x; i < BATCH; i += NTHR) acc += g_row_val[i];
    s[threadIdx.x] = acc;
    __syncthreads();
    for (int off = NTHR / 2; off > 0; off >>= 1) {
        if (threadIdx.x < off) s[threadIdx.x] += s[threadIdx.x + off];
        __syncthreads();
    }
    if (threadIdx.x == 0) out[0] = s[0] * (1.0f / (float)BATCH);
}

extern "C" void kernel_launch(void* const* d_in, const int* in_sizes, int n_in,
                              void* d_out, int out_size) {
    const float* x  = (const float*)d_in[0];
    const float* y  = (const float*)d_in[1];
    // d_in[2] = y_neg: never affects the result, never read.
    const void*  wl = d_in[3];

    build_wl_kernel<<<1, NTHR>>>(wl);
    row_kernel<<<BATCH, NTHR>>>(x, y);
    sum_kernel<<<1, NTHR>>>((float*)d_out);
}

// round 4
// speedup vs baseline: 1.7113x; 1.7113x over previous
#include <cuda_runtime.h>
#include <math.h>

#define BATCH 2048
#define NC    9605
#define NL    8
#define MAXWL 512
#define NTHR  256
#define DETB  32

__device__ int           g_wl_count;
__device__ int           g_wl_idx[MAXWL];
__device__ unsigned char g_wl_mask[MAXWL];
__device__ float         g_row_val[BATCH];
__device__ int           g_flags[DETB][4];   // badint, anyint1, badf, anyf1

__device__ __forceinline__ float sigmoidf_(float v) {
    return 1.0f / (1.0f + expf(-v));   // v=-1e30 -> 0, correct
}
__device__ __forceinline__ unsigned f2k(unsigned u) {          // monotone float->uint
    return (u & 0x80000000u) ? ~u : (u | 0x80000000u);
}
__device__ __forceinline__ float k2f(unsigned k) {             // inverse
    return (k & 0x80000000u) ? __uint_as_float(k ^ 0x80000000u)
                             : __uint_as_float(~k);
}

// ---------------------------------------------------------------------------
// Kernel 1a: dtype sniff for wl_masks (bool may arrive as f32/i32/u8).
// Per-block flag slots (plain stores each call) avoid cross-block reset races.
// ---------------------------------------------------------------------------
__global__ void __launch_bounds__(NTHR) detect_kernel(const void* __restrict__ wlraw) {
    __shared__ int fl[4];
    const int tid = threadIdx.x;
    if (tid < 4) fl[tid] = 0;
    __syncthreads();
    const int NQ = (NL * NC) / 4;                 // 4B slots safe under any dtype
    const int*   ip = (const int*)wlraw;
    const float* fp = (const float*)wlraw;
    for (int i = blockIdx.x * blockDim.x + tid; i < NQ; i += gridDim.x * blockDim.x) {
        int v = ip[i];
        float f = fp[i];
        if (v != 0 && v != 1)          fl[0] = 1;
        if (v == 1)                    fl[1] = 1;
        if (!(f == 0.0f || f == 1.0f)) fl[2] = 1;
        if (f == 1.0f)                 fl[3] = 1;
    }
    __syncthreads();
    if (tid < 4) g_flags[blockIdx.x][tid] = fl[tid];
    if (blockIdx.x == 0 && tid == 0) g_wl_count = 0;
}

// ---------------------------------------------------------------------------
// Kernel 1b: compact whitelist -> (column, 8-bit label mask). 32 blocks.
// ---------------------------------------------------------------------------
__global__ void __launch_bounds__(NTHR) build_wl_kernel(const void* __restrict__ wlraw) {
    __shared__ int mode_s;
    const int tid = threadIdx.x;
    if (tid == 0) {
        int badint = 0, anyint1 = 0, badf = 0, anyf1 = 0;
        for (int j = 0; j < DETB; ++j) {
            badint |= g_flags[j][0]; anyint1 |= g_flags[j][1];
            badf   |= g_flags[j][2]; anyf1   |= g_flags[j][3];
        }
        mode_s = (!badf && anyf1) ? 2 : (!badint ? 1 : 0);  // 2=f32,1=i32,0=u8
        (void)anyint1;
    }
    __syncthreads();
    const int mode = mode_s;
    const int*           ip = (const int*)wlraw;
    const float*         fp = (const float*)wlraw;
    const unsigned char* up = (const unsigned char*)wlraw;

    for (int c = blockIdx.x * blockDim.x + tid; c < NC; c += gridDim.x * blockDim.x) {
        unsigned m = 0;
#pragma unroll
        for (int l = 0; l < NL; ++l) {
            bool on;
            if      (mode == 2) on = (fp[l * NC + c] != 0.0f);
            else if (mode == 1) on = (ip[l * NC + c] != 0);
            else                on = (up[l * NC + c] != 0);
            if (on) m |= (1u << l);
        }
        if (m) {
            int p = atomicAdd(&g_wl_count, 1);
            g_wl_idx[p]  = c;
            g_wl_mask[p] = (unsigned char)m;
        }
    }
}

// ---------------------------------------------------------------------------
// Kernel 2: one block per row.
//  - stage x row as monotone keys in smem (single DRAM stream)
//  - exact 11th-largest via 4-level radix select (256-bin smem histograms)
//  - whitelist maxes / pos bits / union max from smem keys + sparse y gather
// ---------------------------------------------------------------------------
__global__ void __launch_bounds__(NTHR)
row_kernel(const float* __restrict__ x, const float* __restrict__ y) {
    __shared__ unsigned s_keys[NC];
    __shared__ unsigned s_hist[256];
    __shared__ unsigned s_scan[256];
    __shared__ unsigned s_bin, s_want;
    __shared__ unsigned s_lmaxk[NTHR / 32][NL];
    __shared__ unsigned s_unk[NTHR / 32];
    __shared__ unsigned s_pb[NTHR / 32];

    const int b   = blockIdx.x;
    const int tid = threadIdx.x;
    const float* xr = x + (size_t)b * NC;
    const float* yr = y + (size_t)b * NC;

    // ---- phase A: stream row from DRAM, store keys (high MLP, no deps) ----
#pragma unroll 4
    for (int c = tid; c < NC; c += NTHR)
        s_keys[c] = f2k(__float_as_uint(__ldg(xr + c)));
    __syncthreads();

    // ---- exact radix select: 11th largest key, 8 bits per level ----
    unsigned prefix = 0;
    unsigned want   = 11;
#pragma unroll
    for (int lvl = 0; lvl < 4; ++lvl) {
        const int shift = 24 - 8 * lvl;
        s_hist[tid] = 0;
        __syncthreads();

        for (int base = 0; base < NC; base += NTHR) {
            const int c = base + tid;
            bool m = (c < NC);
            unsigned key = 0, bin = 0;
            if (m) {
                key = s_keys[c];
                bin = (key >> shift) & 0xFFu;
                if (lvl > 0) m = ((key >> (shift + 8)) == prefix);
            }
            unsigned act = __ballot_sync(0xffffffffu, m);
            if (m) {
                unsigned grp = __match_any_sync(act, bin);
                if ((int)(tid & 31) == (__ffs(grp) - 1))
                    atomicAdd(&s_hist[bin], (unsigned)__popc(grp));
            }
        }
        __syncthreads();

        // suffix sum over 256 bins (Hillis-Steele)
        const unsigned cnt = s_hist[tid];
        unsigned val = cnt;
        s_scan[tid] = val;
        __syncthreads();
#pragma unroll
        for (int off = 1; off < 256; off <<= 1) {
            const unsigned add = (tid + off < 256) ? s_scan[tid + off] : 0u;
            __syncthreads();
            val += add;
            s_scan[tid] = val;
            __syncthreads();
        }
        const unsigned above = val - cnt;   // count strictly in higher bins
        if (above < want && want <= val) { s_bin = (unsigned)tid; s_want = want - above; }
        __syncthreads();
        prefix = (prefix << 8) | s_bin;
        want   = s_want;
        __syncthreads();
    }
    const unsigned key11 = prefix;          // exact 11th-largest key

    // ---- whitelist gather (x from smem keys, y sparse from DRAM) ----
    const unsigned KNEG = f2k(__float_as_uint(-1e30f));
    const int nwl = g_wl_count;
    unsigned lmaxk[NL];
#pragma unroll
    for (int l = 0; l < NL; ++l) lmaxk[l] = KNEG;
    unsigned unk = KNEG, pos = 0;

    for (int e = tid; e < nwl; e += NTHR) {
        const int      c  = g_wl_idx[e];
        const unsigned m  = g_wl_mask[e];
        const unsigned kv = s_keys[c];
        const float    yv = __ldg(yr + c);
        unk = max(unk, kv);
        if (yv > 0.0f) pos |= m;
#pragma unroll
        for (int l = 0; l < NL; ++l)
            if (m & (1u << l)) lmaxk[l] = max(lmaxk[l], kv);
    }

#pragma unroll
    for (int s = 16; s > 0; s >>= 1) {
#pragma unroll
        for (int l = 0; l < NL; ++l)
            lmaxk[l] = max(lmaxk[l], __shfl_xor_sync(0xffffffffu, lmaxk[l], s));
        unk = max(unk, __shfl_xor_sync(0xffffffffu, unk, s));
        pos |= __shfl_xor_sync(0xffffffffu, pos, s);
    }
    const int warp = tid >> 5, lane = tid & 31;
    if (lane == 0) {
#pragma unroll
        for (int l = 0; l < NL; ++l) s_lmaxk[warp][l] = lmaxk[l];
        s_unk[warp] = unk;
        s_pb[warp]  = pos;
    }
    __syncthreads();

    if (tid == 0) {
#pragma unroll
        for (int w = 1; w < NTHR / 32; ++w) {
#pragma unroll
            for (int l = 0; l < NL; ++l) lmaxk[l] = max(lmaxk[l], s_lmaxk[w][l]);
            unk = max(unk, s_unk[w]);
            pos |= s_pb[w];
        }

        const float thres = fmaxf(sigmoidf_(k2f(key11)), 0.5f);   // ALPHA_OTHER

        unsigned ck = KNEG, ik = KNEG;
#pragma unroll
        for (int l = 0; l < NL; ++l) {
            if (pos & (1u << l)) ck = max(ck, lmaxk[l]);
            else                 ik = max(ik, lmaxk[l]);
        }

        float x1, x2, coef;
        if (pos) {                                   // any_correct
            x1   = sigmoidf_(k2f(ck));
            x2   = fmaxf(sigmoidf_(k2f(ik)), thres); // covers any_incorrect branch
            coef = 1.0f;
        } else {
            x1   = thres;
            x2   = sigmoidf_(k2f(unk));
            coef = 0.5f;                             // 1 - ALPHA
        }

        const float d    = x2 - x1 + 0.1f;           // ALPHA1
        const float rank = (d > 0.0f ? 2.0f : 1.0f) * sigmoidf_(10.0f * d);
        g_row_val[b] = coef * rank;
    }
}

// ---------------------------------------------------------------------------
// Kernel 3: deterministic tree sum -> mean
// ---------------------------------------------------------------------------
__global__ void __launch_bounds__(NTHR)
sum_kernel(float* __restrict__ out) {
    __shared__ float s[NTHR];
    float acc = 0.0f;
    for (int i = threadIdx.x; i < BATCH; i += NTHR) acc += g_row_val[i];
    s[threadIdx.x] = acc;
    __syncthreads();
    for (int off = NTHR / 2; off > 0; off >>= 1) {
        if (threadIdx.x < off) s[threadIdx.x] += s[threadIdx.x + off];
        __syncthreads();
    }
    if (threadIdx.x == 0) out[0] = s[0] * (1.0f / (float)BATCH);
}

extern "C" void kernel_launch(void* const* d_in, const int* in_sizes, int n_in,
                              void* d_out, int out_size) {
    const float* x  = (const float*)d_in[0];
    const float* y  = (const float*)d_in[1];
    // d_in[2] = y_neg: never affects the result, never read.
    const void*  wl = d_in[3];

    detect_kernel<<<DETB, NTHR>>>(wl);
    build_wl_kernel<<<DETB, NTHR>>>(wl);
    row_kernel<<<BATCH, NTHR>>>(x, y);
    sum_kernel<<<1, NTHR>>>((float*)d_out);
}